// round 14
// baseline (speedup 1.0000x reference)
#include <cuda_runtime.h>
#include <cuda_bf16.h>
#include <cstdint>

// Problem constants
#define S    2048
#define HID  2560
#define NH   32
#define HD   80
#define N_QKV (3*HID)          // 7680
#define SCALE 0.11180339887498949f   // 80^-0.5

// ---------------- scratch (device globals; no allocs allowed) ---------------
__device__ float g_q[NH * S * HD];
__device__ float g_k[NH * S * HD];
__device__ float g_posf[S];

__device__ __nv_bfloat16 g_a_hi[S * HID],      g_a_lo[S * HID];
__device__ __nv_bfloat16 g_wqkv_hi[N_QKV*HID], g_wqkv_lo[N_QKV*HID];
__device__ __nv_bfloat16 g_wout_hi[HID*HID],   g_wout_lo[HID*HID];
__device__ __nv_bfloat16 g_at_hi[S * HID],     g_at_lo[S * HID];

__device__ __nv_bfloat16 g_qh[NH*S*HD], g_ql[NH*S*HD];
__device__ __nv_bfloat16 g_kh[NH*S*HD], g_kl[NH*S*HD];
__device__ __nv_bfloat16 g_vh[NH*S*HD], g_vl[NH*S*HD];

// ---------------- PTX helpers ------------------------------------------------
__device__ __forceinline__ uint32_t smem_u32(const void* p) {
    return (uint32_t)__cvta_generic_to_shared((void*)p);
}
__device__ __forceinline__ void cp16(uint32_t s, const void* g) {
    asm volatile("cp.async.cg.shared.global [%0], [%1], 16;" :: "r"(s), "l"(g) : "memory");
}
__device__ __forceinline__ void ldsm_x4(uint32_t* r, uint32_t addr) {
    asm volatile("ldmatrix.sync.aligned.m8n8.x4.shared.b16 {%0,%1,%2,%3}, [%4];"
                 : "=r"(r[0]), "=r"(r[1]), "=r"(r[2]), "=r"(r[3]) : "r"(addr));
}
__device__ __forceinline__ void ldsm_x4t(uint32_t* r, uint32_t addr) {
    asm volatile("ldmatrix.sync.aligned.m8n8.x4.trans.shared.b16 {%0,%1,%2,%3}, [%4];"
                 : "=r"(r[0]), "=r"(r[1]), "=r"(r[2]), "=r"(r[3]) : "r"(addr));
}
__device__ __forceinline__ void mma16816(float* d, const uint32_t* a, const uint32_t* b) {
    asm volatile("mma.sync.aligned.m16n8k16.row.col.f32.bf16.bf16.f32 "
                 "{%0,%1,%2,%3}, {%4,%5,%6,%7}, {%8,%9}, {%0,%1,%2,%3};"
                 : "+f"(d[0]), "+f"(d[1]), "+f"(d[2]), "+f"(d[3])
                 : "r"(a[0]), "r"(a[1]), "r"(a[2]), "r"(a[3]), "r"(b[0]), "r"(b[1]));
}
__device__ __forceinline__ void split2(float a, float b, uint32_t& hi, uint32_t& lo) {
    __nv_bfloat162 h, l;
    h.x = __float2bfloat16(a);
    h.y = __float2bfloat16(b);
    l.x = __float2bfloat16(a - __bfloat162float(h.x));
    l.y = __float2bfloat16(b - __bfloat162float(h.y));
    hi = *(uint32_t*)&h;
    lo = *(uint32_t*)&l;
}

// ---------------- HMMA GEMM (unchanged from R12/R13 best) --------------------
#define BMg 128
#define BNg 128
#define RSg 72
#define TENg (128*RSg)
#define STAGEg (2*TENg)
#define GEMM_SMEM (3*STAGEg*2)

__global__ __launch_bounds__(256, 2)
void mma_gemm(const __nv_bfloat16* __restrict__ Ahi, const __nv_bfloat16* __restrict__ Alo,
              const __nv_bfloat16* __restrict__ Bhi, const __nv_bfloat16* __restrict__ Blo,
              float* __restrict__ C, int K, int N, int mode)
{
    extern __shared__ __align__(128) __nv_bfloat16 sm[];
    const int tid  = threadIdx.x;
    const int wid  = tid >> 5;
    const int lane = tid & 31;
    const int wr   = wid >> 2;
    const int wc   = wid & 3;
    const int rowBase = blockIdx.y * BMg;
    const int colBase = blockIdx.x * BNg;
    const uint32_t smbase = smem_u32(sm);

    float acc[4][4][4];
#pragma unroll
    for (int i = 0; i < 4; i++)
#pragma unroll
        for (int j = 0; j < 4; j++)
#pragma unroll
            for (int k = 0; k < 4; k++) acc[i][j][k] = 0.f;

    const int NC = K >> 5;

    auto load_stage = [&](int c) {
        const int kt = c << 5;
        const uint32_t sb = smbase + (uint32_t)(c % 3) * (STAGEg * 2);
#pragma unroll
        for (int t = 0; t < 8; t++) {
            int idx = tid + t * 256;
            int isB = idx >> 10;
            int rem = idx & 1023;
            int hl  = rem >> 9;
            int r2  = rem & 511;
            int row = r2 >> 2, seg = r2 & 3;
            const __nv_bfloat16* src = isB
                ? ((hl ? Blo : Bhi) + (size_t)(colBase + row) * K + kt + seg * 8)
                : ((hl ? Alo : Ahi) + (size_t)(rowBase + row) * K + kt + seg * 8);
            cp16(sb + (uint32_t)(isB * TENg + row * RSg + hl * 32 + seg * 8) * 2, src);
        }
        asm volatile("cp.async.commit_group;" ::: "memory");
    };

    load_stage(0);
    load_stage(1);

    for (int c = 0; c < NC; c++) {
        asm volatile("cp.async.wait_group 1;" ::: "memory");
        __syncthreads();
        if (c + 2 < NC) load_stage(c + 2);
        else asm volatile("cp.async.commit_group;" ::: "memory");

        const uint32_t sb = smbase + (uint32_t)(c % 3) * (STAGEg * 2);
#pragma unroll
        for (int ks = 0; ks < 2; ks++) {
            const int kof = ks * 16;
            uint32_t ah[4][4], al[4][4];
#pragma unroll
            for (int mf = 0; mf < 4; mf++) {
                int row = wr * 64 + mf * 16 + (lane & 15);
                int col = kof + (lane >> 4) * 8;
                uint32_t ad = sb + (uint32_t)(row * RSg + col) * 2;
                ldsm_x4(ah[mf], ad);
                ldsm_x4(al[mf], ad + 64);
            }
            uint32_t bh[2][4], bl[2][4];
#pragma unroll
            for (int np = 0; np < 2; np++) {
                int brow = wc * 32 + np * 16 + ((lane >> 4) & 1) * 8 + (lane & 7);
                int bcol = kof + ((lane >> 3) & 1) * 8;
                uint32_t bd = sb + TENg * 2 + (uint32_t)(brow * RSg + bcol) * 2;
                ldsm_x4(bh[np], bd);
                ldsm_x4(bl[np], bd + 64);
            }
#pragma unroll
            for (int mf = 0; mf < 4; mf++)
#pragma unroll
                for (int np = 0; np < 2; np++) {
                    mma16816(acc[mf][np*2],   ah[mf], &bh[np][0]);
                    mma16816(acc[mf][np*2+1], ah[mf], &bh[np][2]);
                }
#pragma unroll
            for (int mf = 0; mf < 4; mf++)
#pragma unroll
                for (int np = 0; np < 2; np++) {
                    mma16816(acc[mf][np*2],   ah[mf], &bl[np][0]);
                    mma16816(acc[mf][np*2+1], ah[mf], &bl[np][2]);
                }
#pragma unroll
            for (int mf = 0; mf < 4; mf++)
#pragma unroll
                for (int np = 0; np < 2; np++) {
                    mma16816(acc[mf][np*2],   al[mf], &bh[np][0]);
                    mma16816(acc[mf][np*2+1], al[mf], &bh[np][2]);
                }
        }
    }

#pragma unroll
    for (int mf = 0; mf < 4; mf++) {
#pragma unroll
        for (int nf = 0; nf < 4; nf++) {
            int row = rowBase + wr * 64 + mf * 16 + (lane >> 2);
            int col = colBase + wc * 32 + nf * 8 + (lane & 3) * 2;
            if (mode == 0) {
                *(float2*)(C + (size_t)row * N + col) =
                    make_float2(acc[mf][nf][0], acc[mf][nf][1]);
                *(float2*)(C + (size_t)(row + 8) * N + col) =
                    make_float2(acc[mf][nf][2], acc[mf][nf][3]);
            } else {
                int p   = col / HID;
                int rem = col - p * HID;
                int h   = rem / HD;
                int d   = rem - h * HD;
                size_t o0 = ((size_t)h * S + row) * HD + d;
                size_t o1 = ((size_t)h * S + row + 8) * HD + d;
                if (p == 2) {
                    uint32_t hi, lo;
                    split2(acc[mf][nf][0], acc[mf][nf][1], hi, lo);
                    *(uint32_t*)&g_vh[o0] = hi;
                    *(uint32_t*)&g_vl[o0] = lo;
                    split2(acc[mf][nf][2], acc[mf][nf][3], hi, lo);
                    *(uint32_t*)&g_vh[o1] = hi;
                    *(uint32_t*)&g_vl[o1] = lo;
                } else {
                    float* dst = (p == 0) ? g_q : g_k;
                    *(float2*)(&dst[o0]) = make_float2(acc[mf][nf][0], acc[mf][nf][1]);
                    *(float2*)(&dst[o1]) = make_float2(acc[mf][nf][2], acc[mf][nf][3]);
                }
            }
        }
    }
}

// ---------------- conversions ------------------------------------------------
__global__ void conv_split(const float* __restrict__ x, __nv_bfloat16* __restrict__ hi,
                           __nv_bfloat16* __restrict__ lo, int n)
{
    int i = blockIdx.x * blockDim.x + threadIdx.x;
    if (i >= n) return;
    float v = x[i];
    __nv_bfloat16 h = __float2bfloat16(v);
    hi[i] = h;
    lo[i] = __float2bfloat16(v - __bfloat162float(h));
}

__global__ void convt_split(const float* __restrict__ W, __nv_bfloat16* __restrict__ hi,
                            __nv_bfloat16* __restrict__ lo, int K, int N)
{
    __shared__ float t[32][33];
    int n0 = blockIdx.x * 32, k0 = blockIdx.y * 32;
    for (int r = threadIdx.y; r < 32; r += 8)
        t[r][threadIdx.x] = W[(size_t)(k0 + r) * N + n0 + threadIdx.x];
    __syncthreads();
    for (int r = threadIdx.y; r < 32; r += 8) {
        float v = t[threadIdx.x][r];
        __nv_bfloat16 h = __float2bfloat16(v);
        size_t o = (size_t)(n0 + r) * K + k0 + threadIdx.x;
        hi[o] = h;
        lo[o] = __float2bfloat16(v - __bfloat162float(h));
    }
}

__device__ __forceinline__ void wsplit(__nv_bfloat16* hi, __nv_bfloat16* lo,
                                       size_t off, float v) {
    __nv_bfloat16 h = __float2bfloat16(v);
    hi[off] = h;
    lo[off] = __float2bfloat16(v - __bfloat162float(h));
}

__global__ void rope_split(const int* __restrict__ pos)
{
    int idx = blockIdx.x * blockDim.x + threadIdx.x;
    if (idx < S) g_posf[idx] = (float)pos[idx];
    int d48 = idx % 48;
    int rem = idx / 48;
    int s = rem & (S - 1);
    int h = rem >> 11;
    if (h >= NH) return;
    size_t base = ((size_t)h * S + s) * HD;
    if (d48 < 32) {
        int d = d48;
        float posf = (float)pos[s];
        float inv  = exp2f(-0.415241011861f * (float)d);
        float ang  = posf * inv;
        float c, sn;
        sincosf(ang, &sn, &c);
        float q1 = g_q[base + d], q2 = g_q[base + d + 32];
        float k1 = g_k[base + d], k2 = g_k[base + d + 32];
        wsplit(g_qh, g_ql, base + d,      q1 * c - q2 * sn);
        wsplit(g_qh, g_ql, base + d + 32, q2 * c + q1 * sn);
        wsplit(g_kh, g_kl, base + d,      k1 * c - k2 * sn);
        wsplit(g_kh, g_kl, base + d + 32, k2 * c + k1 * sn);
    } else {
        int d = d48 + 32;
        wsplit(g_qh, g_ql, base + d, g_q[base + d]);
        wsplit(g_kh, g_kl, base + d, g_k[base + d]);
    }
}

// ---------------- HMMA flash attention: 2D warp split + k-half merge ---------
// Q-tile 128, 8 warps as 4(q-band 32) x 2(kpos-half 32). K-tile 64.
// Q hi/lo in smem. 3-stage ring, one barrier per chunk. Exact end merge.
#define AQB 128
#define AKB 64
#define QRS 168                         // Q row stride elems (80 hi | 80 lo | 8 pad)
#define Q_SZ (128*QRS*2)                // 43008 bytes
#define ARS 88                          // K/V row stride elems
#define T_ELEMS (AKB*ARS)               // 5632
#define KPOS_OFF (4*T_ELEMS*2)          // 45056
#define ASTAGE (KPOS_OFF + 256)         // 45312
#define ATTN_SMEM (Q_SZ + 3*ASTAGE)     // 178944

__global__ __launch_bounds__(256)
void attn_mma()
{
    extern __shared__ char smbuf[];
    const int h     = blockIdx.y;
    const int qtile = gridDim.x - 1 - blockIdx.x;
    const int q0    = qtile * AQB;
    const int tid   = threadIdx.x;
    const int wid   = tid >> 5;
    const int lane  = tid & 31;
    const int wr    = wid >> 1;          // 0..3: q band of 32 rows
    const int wc    = wid & 1;           // 0..1: kpos half of 32
    const int cp    = (lane & 3) * 2;
    const int mq    = lane >> 3;
    const uint32_t sb  = smem_u32(smbuf);
    const uint32_t stb = sb + Q_SZ;

    // per-thread q rows: idx = mf*2+j -> row = q0 + wr*32 + mf*16 + j*8 + (lane>>2)
    const int rbase = q0 + wr * 32 + (lane >> 2);
    float qp[4];
#pragma unroll
    for (int idx = 0; idx < 4; idx++)
        qp[idx] = g_posf[rbase + (idx >> 1) * 16 + (idx & 1) * 8];
    const float slope = exp2f(-0.25f * (float)(h + 1));

    float o[2][10][4];
#pragma unroll
    for (int mf = 0; mf < 2; mf++)
#pragma unroll
        for (int nf = 0; nf < 10; nf++)
#pragma unroll
            for (int e = 0; e < 4; e++) o[mf][nf][e] = 0.f;
    float m[4] = {-1e30f, -1e30f, -1e30f, -1e30f};
    float l[4] = {0.f, 0.f, 0.f, 0.f};

    const int NT = qtile * 2 + 2;

    // ---- load Q (hi+lo) into smem (group 0) ----
    {
#pragma unroll
        for (int it = 0; it < 10; it++) {
            int idx = it * 256 + tid;            // 0..2559
            int hl  = idx >= 1280;
            int r2  = hl ? idx - 1280 : idx;
            int row = r2 / 10, seg = r2 - row * 10;
            const __nv_bfloat16* src = (hl ? g_ql : g_qh)
                + ((size_t)h * S + q0 + row) * HD + seg * 8;
            cp16(sb + (uint32_t)(row * QRS + hl * 80 + seg * 8) * 2, src);
        }
        asm volatile("cp.async.commit_group;" ::: "memory");
    }

    auto issue = [&](int t) {
        const uint32_t dst = stb + (uint32_t)(t % 3) * ASTAGE;
        const int kt = t * AKB;
#pragma unroll
        for (int it = 0; it < 10; it++) {
            int idx = it * 256 + tid;            // 0..2559
            int tensor = idx / 640;
            int rem = idx - tensor * 640;
            int row = rem / 10, seg = rem - row * 10;
            const __nv_bfloat16* base =
                (tensor == 0) ? g_kh : (tensor == 1) ? g_kl : (tensor == 2) ? g_vh : g_vl;
            const __nv_bfloat16* src = base + ((size_t)h * S + kt + row) * HD + seg * 8;
            cp16(dst + (uint32_t)tensor * (T_ELEMS * 2) + (uint32_t)(row * ARS + seg * 8) * 2, src);
        }
        if (tid < 16) cp16(dst + KPOS_OFF + tid * 16, g_posf + kt + tid * 4);
        asm volatile("cp.async.commit_group;" ::: "memory");
    };

    issue(0);
    issue(1);

    for (int t = 0; t < NT; t++) {
        asm volatile("cp.async.wait_group 1;" ::: "memory");
        __syncthreads();
        if (t + 2 < NT) issue(t + 2);
        else asm volatile("cp.async.commit_group;" ::: "memory");

        const uint32_t st = stb + (uint32_t)(t % 3) * ASTAGE;
        const float* kposb = (const float*)(smbuf + Q_SZ + (size_t)(t % 3) * ASTAGE + KPOS_OFF);

        // ---- S = Q K^T (bf16x3) : warp tile 32 q x 32 kpos ----
        float accs[2][4][4];
#pragma unroll
        for (int mf = 0; mf < 2; mf++)
#pragma unroll
            for (int nf = 0; nf < 4; nf++)
#pragma unroll
                for (int e = 0; e < 4; e++) accs[mf][nf][e] = 0.f;

#pragma unroll
        for (int ks = 0; ks < 5; ks++) {
            uint32_t qh[2][4], ql_[2][4];
#pragma unroll
            for (int mf = 0; mf < 2; mf++) {
                uint32_t qa = sb + (uint32_t)((wr * 32 + mf * 16 + (lane & 15)) * QRS
                                              + ks * 16 + (lane >> 4) * 8) * 2;
                ldsm_x4(qh[mf], qa);
                ldsm_x4(ql_[mf], qa + 160);
            }
            uint32_t bh[2][4], bl[2][4];
#pragma unroll
            for (int np = 0; np < 2; np++) {
                uint32_t row = (uint32_t)(wc * 32 + (np * 2 + (mq >> 1)) * 8 + (lane & 7));
                uint32_t col = (uint32_t)(ks * 16 + (mq & 1) * 8);
                uint32_t ad = st + (row * ARS + col) * 2;
                ldsm_x4(bh[np], ad);
                ldsm_x4(bl[np], ad + T_ELEMS * 2);
            }
#pragma unroll
            for (int mf = 0; mf < 2; mf++)
#pragma unroll
                for (int np = 0; np < 2; np++) {
                    mma16816(accs[mf][np*2],   qh[mf], &bh[np][0]);
                    mma16816(accs[mf][np*2+1], qh[mf], &bh[np][2]);
                }
#pragma unroll
            for (int mf = 0; mf < 2; mf++)
#pragma unroll
                for (int np = 0; np < 2; np++) {
                    mma16816(accs[mf][np*2],   qh[mf], &bl[np][0]);
                    mma16816(accs[mf][np*2+1], qh[mf], &bl[np][2]);
                }
#pragma unroll
            for (int mf = 0; mf < 2; mf++)
#pragma unroll
                for (int np = 0; np < 2; np++) {
                    mma16816(accs[mf][np*2],   ql_[mf], &bh[np][0]);
                    mma16816(accs[mf][np*2+1], ql_[mf], &bh[np][2]);
                }
        }

        // ---- masked/biased online softmax (per k-half) ----
        float mx[4] = {-1e30f, -1e30f, -1e30f, -1e30f};
#pragma unroll
        for (int mf = 0; mf < 2; mf++)
#pragma unroll
            for (int nf = 0; nf < 4; nf++) {
                float2 kc = *(const float2*)(kposb + wc * 32 + nf * 8 + cp);
                float b0 = slope * kc.x, b1 = slope * kc.y;
                float s0 = (kc.x <= qp[mf*2])   ? fmaf(accs[mf][nf][0], SCALE, b0) : -1e30f;
                float s1 = (kc.y <= qp[mf*2])   ? fmaf(accs[mf][nf][1], SCALE, b1) : -1e30f;
                float s2 = (kc.x <= qp[mf*2+1]) ? fmaf(accs[mf][nf][2], SCALE, b0) : -1e30f;
                float s3 = (kc.y <= qp[mf*2+1]) ? fmaf(accs[mf][nf][3], SCALE, b1) : -1e30f;
                accs[mf][nf][0] = s0; accs[mf][nf][1] = s1;
                accs[mf][nf][2] = s2; accs[mf][nf][3] = s3;
                mx[mf*2]   = fmaxf(mx[mf*2],   fmaxf(s0, s1));
                mx[mf*2+1] = fmaxf(mx[mf*2+1], fmaxf(s2, s3));
            }
#pragma unroll
        for (int idx = 0; idx < 4; idx++) {
            mx[idx] = fmaxf(mx[idx], __shfl_xor_sync(0xFFFFFFFFu, mx[idx], 1));
            mx[idx] = fmaxf(mx[idx], __shfl_xor_sync(0xFFFFFFFFu, mx[idx], 2));
        }
        float corr[4];
#pragma unroll
        for (int idx = 0; idx < 4; idx++) {
            float mn = fmaxf(m[idx], mx[idx]);
            corr[idx] = __expf(m[idx] - mn);
            m[idx] = mn;
        }
        float sum[4] = {0.f, 0.f, 0.f, 0.f};
#pragma unroll
        for (int mf = 0; mf < 2; mf++)
#pragma unroll
            for (int nf = 0; nf < 4; nf++) {
                float p0 = __expf(accs[mf][nf][0] - m[mf*2]);
                float p1 = __expf(accs[mf][nf][1] - m[mf*2]);
                float p2 = __expf(accs[mf][nf][2] - m[mf*2+1]);
                float p3 = __expf(accs[mf][nf][3] - m[mf*2+1]);
                accs[mf][nf][0] = p0; accs[mf][nf][1] = p1;
                accs[mf][nf][2] = p2; accs[mf][nf][3] = p3;
                sum[mf*2] += p0 + p1; sum[mf*2+1] += p2 + p3;
            }
#pragma unroll
        for (int idx = 0; idx < 4; idx++)
            l[idx] = l[idx] * corr[idx] + sum[idx];
#pragma unroll
        for (int mf = 0; mf < 2; mf++)
#pragma unroll
            for (int nf = 0; nf < 10; nf++) {
                o[mf][nf][0] *= corr[mf*2];   o[mf][nf][1] *= corr[mf*2];
                o[mf][nf][2] *= corr[mf*2+1]; o[mf][nf][3] *= corr[mf*2+1];
            }

        // ---- P fragments (hi/lo) ----
        uint32_t ph[2][2][4], pl[2][2][4];
#pragma unroll
        for (int mf = 0; mf < 2; mf++)
#pragma unroll
            for (int ks2 = 0; ks2 < 2; ks2++) {
                split2(accs[mf][2*ks2][0],   accs[mf][2*ks2][1],   ph[mf][ks2][0], pl[mf][ks2][0]);
                split2(accs[mf][2*ks2][2],   accs[mf][2*ks2][3],   ph[mf][ks2][1], pl[mf][ks2][1]);
                split2(accs[mf][2*ks2+1][0], accs[mf][2*ks2+1][1], ph[mf][ks2][2], pl[mf][ks2][2]);
                split2(accs[mf][2*ks2+1][2], accs[mf][2*ks2+1][3], ph[mf][ks2][3], pl[mf][ks2][3]);
            }

        // ---- O += P V (bf16x3), warp's 32 kpos only ----
#pragma unroll
        for (int ks2 = 0; ks2 < 2; ks2++) {
            uint32_t vh[5][4], vl[5][4];
#pragma unroll
            for (int nfp = 0; nfp < 5; nfp++) {
                uint32_t row = (uint32_t)(wc * 32 + ks2 * 16 + (mq & 1) * 8 + (lane & 7));
                uint32_t col = (uint32_t)((nfp * 2 + (mq >> 1)) * 8);
                uint32_t ad = st + 2 * (T_ELEMS * 2) + (row * ARS + col) * 2;
                ldsm_x4t(vh[nfp], ad);
                ldsm_x4t(vl[nfp], ad + T_ELEMS * 2);
            }
#pragma unroll
            for (int mf = 0; mf < 2; mf++)
#pragma unroll
                for (int nfp = 0; nfp < 5; nfp++) {
                    mma16816(o[mf][nfp*2],   ph[mf][ks2], &vh[nfp][0]);
                    mma16816(o[mf][nfp*2+1], ph[mf][ks2], &vh[nfp][2]);
                }
#pragma unroll
            for (int mf = 0; mf < 2; mf++)
#pragma unroll
                for (int nfp = 0; nfp < 5; nfp++) {
                    mma16816(o[mf][nfp*2],   ph[mf][ks2], &vl[nfp][0]);
                    mma16816(o[mf][nfp*2+1], ph[mf][ks2], &vl[nfp][2]);
                }
#pragma unroll
            for (int mf = 0; mf < 2; mf++)
#pragma unroll
                for (int nfp = 0; nfp < 5; nfp++) {
                    mma16816(o[mf][nfp*2],   pl[mf][ks2], &vh[nfp][0]);
                    mma16816(o[mf][nfp*2+1], pl[mf][ks2], &vh[nfp][2]);
                }
        }
    }

    // ---- per-warp l reduction (within its 32-col slice) ----
#pragma unroll
    for (int idx = 0; idx < 4; idx++) {
        l[idx] += __shfl_xor_sync(0xFFFFFFFFu, l[idx], 1);
        l[idx] += __shfl_xor_sync(0xFFFFFFFFu, l[idx], 2);
    }

    // ---- merge the two k-halves (exact) ----
    __syncthreads();                     // all compute done; stage smem reusable
    float* ex = (float*)smbuf;
    const int slot = (wr * 32 + lane) * 90;
    if (wc == 1) {
        float* p = ex + slot;
#pragma unroll
        for (int mf = 0; mf < 2; mf++)
#pragma unroll
            for (int nf = 0; nf < 10; nf++)
#pragma unroll
                for (int e = 0; e < 4; e++)
                    p[(mf * 10 + nf) * 4 + e] = o[mf][nf][e];
#pragma unroll
        for (int idx = 0; idx < 4; idx++) { p[80 + idx] = m[idx]; p[84 + idx] = l[idx]; }
    }
    __syncthreads();
    if (wc == 0) {
        const float* p = ex + slot;
        float ca[4], cb[4], inv[4];
#pragma unroll
        for (int idx = 0; idx < 4; idx++) {
            float mb = p[80 + idx], lb = p[84 + idx];
            float mm = fmaxf(m[idx], mb);
            ca[idx] = __expf(m[idx] - mm);
            cb[idx] = __expf(mb - mm);
            inv[idx] = 1.f / (ca[idx] * l[idx] + cb[idx] * lb);
        }
#pragma unroll
        for (int mf = 0; mf < 2; mf++) {
            size_t ob0 = (size_t)(rbase + mf * 16) * HID + h * HD;
            size_t ob1 = (size_t)(rbase + mf * 16 + 8) * HID + h * HD;
#pragma unroll
            for (int nf = 0; nf < 10; nf++) {
                const float* q2 = p + (mf * 10 + nf) * 4;
                float v0 = (ca[mf*2]   * o[mf][nf][0] + cb[mf*2]   * q2[0]) * inv[mf*2];
                float v1 = (ca[mf*2]   * o[mf][nf][1] + cb[mf*2]   * q2[1]) * inv[mf*2];
                float v2 = (ca[mf*2+1] * o[mf][nf][2] + cb[mf*2+1] * q2[2]) * inv[mf*2+1];
                float v3 = (ca[mf*2+1] * o[mf][nf][3] + cb[mf*2+1] * q2[3]) * inv[mf*2+1];
                int col = nf * 8 + cp;
                uint32_t hi, lo;
                split2(v0, v1, hi, lo);
                *(uint32_t*)&g_at_hi[ob0 + col] = hi;
                *(uint32_t*)&g_at_lo[ob0 + col] = lo;
                split2(v2, v3, hi, lo);
                *(uint32_t*)&g_at_hi[ob1 + col] = hi;
                *(uint32_t*)&g_at_lo[ob1 + col] = lo;
            }
        }
    }
}

// ---------------- launch -------------------------------------------------------
extern "C" void kernel_launch(void* const* d_in, const int* in_sizes, int n_in,
                              void* d_out, int out_size)
{
    const int*   pos  = nullptr;
    const float* hs   = nullptr;
    const float* wqkv = nullptr;
    const float* wout = nullptr;
    for (int i = 0; i < n_in; i++) {
        switch (in_sizes[i]) {
            case S:           pos  = (const int*)d_in[i];   break;
            case S * HID:     hs   = (const float*)d_in[i]; break;
            case HID * N_QKV: wqkv = (const float*)d_in[i]; break;
            case HID * HID:   wout = (const float*)d_in[i]; break;
        }
    }
    if (!pos || !hs || !wqkv || !wout) return;

    cudaFuncSetAttribute(mma_gemm, cudaFuncAttributeMaxDynamicSharedMemorySize, GEMM_SMEM);
    cudaFuncSetAttribute(attn_mma, cudaFuncAttributeMaxDynamicSharedMemorySize, ATTN_SMEM);

    __nv_bfloat16 *ahi, *alo, *wqh, *wql, *woh, *wol, *ath, *atl;
    cudaGetSymbolAddress((void**)&ahi, g_a_hi);
    cudaGetSymbolAddress((void**)&alo, g_a_lo);
    cudaGetSymbolAddress((void**)&wqh, g_wqkv_hi);
    cudaGetSymbolAddress((void**)&wql, g_wqkv_lo);
    cudaGetSymbolAddress((void**)&woh, g_wout_hi);
    cudaGetSymbolAddress((void**)&wol, g_wout_lo);
    cudaGetSymbolAddress((void**)&ath, g_at_hi);
    cudaGetSymbolAddress((void**)&atl, g_at_lo);

    // conversions
    conv_split<<<(S * HID) / 256, 256>>>(hs, ahi, alo, S * HID);
    convt_split<<<dim3(N_QKV / 32, HID / 32), dim3(32, 8)>>>(wqkv, wqh, wql, HID, N_QKV);
    convt_split<<<dim3(HID / 32, HID / 32), dim3(32, 8)>>>(wout, woh, wol, HID, HID);

    // 1) QKV projection (scatter epilogue: q,k fp32; v bf16 hi/lo direct)
    mma_gemm<<<dim3(N_QKV / BNg, S / BMg), 256, GEMM_SMEM>>>(ahi, alo, wqh, wql, nullptr, HID, N_QKV, 1);

    // 2) fused RoPE + split for q,k (+ pos -> float)
    rope_split<<<(NH * S * 48) / 256, 256>>>(pos);

    // 3) flash attention (HMMA, 2D warp split, k-half merge)
    attn_mma<<<dim3(S / AQB, NH), 256, ATTN_SMEM>>>();

    // 4) output projection
    mma_gemm<<<dim3(HID / BNg, S / BMg), 256, GEMM_SMEM>>>(ath, atl, woh, wol, (float*)d_out, HID, HID, 0);
}

// round 15
// speedup vs baseline: 1.0740x; 1.0740x over previous
#include <cuda_runtime.h>
#include <cuda_bf16.h>
#include <cstdint>

// Problem constants
#define S    2048
#define HID  2560
#define NH   32
#define HD   80
#define N_QKV (3*HID)          // 7680
#define SCALE 0.11180339887498949f   // 80^-0.5

// ---------------- scratch (device globals; no allocs allowed) ---------------
__device__ float g_part[2 * S * N_QKV];     // split-K partials (reused by out-proj)
__device__ float g_posf[S];

__device__ __nv_bfloat16 g_a_hi[S * HID],      g_a_lo[S * HID];
__device__ __nv_bfloat16 g_wqkv_hi[N_QKV*HID], g_wqkv_lo[N_QKV*HID];
__device__ __nv_bfloat16 g_wout_hi[HID*HID],   g_wout_lo[HID*HID];
__device__ __nv_bfloat16 g_at_hi[S * HID],     g_at_lo[S * HID];

__device__ __nv_bfloat16 g_qh[NH*S*HD], g_ql[NH*S*HD];
__device__ __nv_bfloat16 g_kh[NH*S*HD], g_kl[NH*S*HD];
__device__ __nv_bfloat16 g_vh[NH*S*HD], g_vl[NH*S*HD];

// ---------------- PTX helpers ------------------------------------------------
__device__ __forceinline__ uint32_t smem_u32(const void* p) {
    return (uint32_t)__cvta_generic_to_shared((void*)p);
}
__device__ __forceinline__ void cp16(uint32_t s, const void* g) {
    asm volatile("cp.async.cg.shared.global [%0], [%1], 16;" :: "r"(s), "l"(g) : "memory");
}
__device__ __forceinline__ void ldsm_x4(uint32_t* r, uint32_t addr) {
    asm volatile("ldmatrix.sync.aligned.m8n8.x4.shared.b16 {%0,%1,%2,%3}, [%4];"
                 : "=r"(r[0]), "=r"(r[1]), "=r"(r[2]), "=r"(r[3]) : "r"(addr));
}
__device__ __forceinline__ void ldsm_x4t(uint32_t* r, uint32_t addr) {
    asm volatile("ldmatrix.sync.aligned.m8n8.x4.trans.shared.b16 {%0,%1,%2,%3}, [%4];"
                 : "=r"(r[0]), "=r"(r[1]), "=r"(r[2]), "=r"(r[3]) : "r"(addr));
}
__device__ __forceinline__ void mma16816(float* d, const uint32_t* a, const uint32_t* b) {
    asm volatile("mma.sync.aligned.m16n8k16.row.col.f32.bf16.bf16.f32 "
                 "{%0,%1,%2,%3}, {%4,%5,%6,%7}, {%8,%9}, {%0,%1,%2,%3};"
                 : "+f"(d[0]), "+f"(d[1]), "+f"(d[2]), "+f"(d[3])
                 : "r"(a[0]), "r"(a[1]), "r"(a[2]), "r"(a[3]), "r"(b[0]), "r"(b[1]));
}
__device__ __forceinline__ void split2(float a, float b, uint32_t& hi, uint32_t& lo) {
    __nv_bfloat162 h, l;
    h.x = __float2bfloat16(a);
    h.y = __float2bfloat16(b);
    l.x = __float2bfloat16(a - __bfloat162float(h.x));
    l.y = __float2bfloat16(b - __bfloat162float(h.y));
    hi = *(uint32_t*)&h;
    lo = *(uint32_t*)&l;
}

// ---------------- HMMA GEMM with split-K -------------------------------------
// D_z[M,N] = A[M, koff:koff+KS] @ B[N, koff:koff+KS]^T (bf16x3 split).
// 128x128 tile, K-chunk 32, 3-stage ring, one barrier/chunk, 2 CTAs/SM.
#define BMg 128
#define BNg 128
#define RSg 72
#define TENg (128*RSg)
#define STAGEg (2*TENg)
#define GEMM_SMEM (3*STAGEg*2)

__global__ __launch_bounds__(256, 2)
void mma_gemm(const __nv_bfloat16* __restrict__ Ahi, const __nv_bfloat16* __restrict__ Alo,
              const __nv_bfloat16* __restrict__ Bhi, const __nv_bfloat16* __restrict__ Blo,
              float* __restrict__ C, int K, int N, int KS)
{
    extern __shared__ __align__(128) __nv_bfloat16 sm[];
    const int tid  = threadIdx.x;
    const int wid  = tid >> 5;
    const int lane = tid & 31;
    const int wr   = wid >> 2;
    const int wc   = wid & 3;
    const int rowBase = blockIdx.y * BMg;
    const int colBase = blockIdx.x * BNg;
    const int koff    = blockIdx.z * KS;
    C += (size_t)blockIdx.z * (size_t)(gridDim.y * BMg) * N;
    const uint32_t smbase = smem_u32(sm);

    float acc[4][4][4];
#pragma unroll
    for (int i = 0; i < 4; i++)
#pragma unroll
        for (int j = 0; j < 4; j++)
#pragma unroll
            for (int k = 0; k < 4; k++) acc[i][j][k] = 0.f;

    const int NC = KS >> 5;

    auto load_stage = [&](int c) {
        const int kt = koff + (c << 5);
        const uint32_t sb = smbase + (uint32_t)(c % 3) * (STAGEg * 2);
#pragma unroll
        for (int t = 0; t < 8; t++) {
            int idx = tid + t * 256;
            int isB = idx >> 10;
            int rem = idx & 1023;
            int hl  = rem >> 9;
            int r2  = rem & 511;
            int row = r2 >> 2, seg = r2 & 3;
            const __nv_bfloat16* src = isB
                ? ((hl ? Blo : Bhi) + (size_t)(colBase + row) * K + kt + seg * 8)
                : ((hl ? Alo : Ahi) + (size_t)(rowBase + row) * K + kt + seg * 8);
            cp16(sb + (uint32_t)(isB * TENg + row * RSg + hl * 32 + seg * 8) * 2, src);
        }
        asm volatile("cp.async.commit_group;" ::: "memory");
    };

    load_stage(0);
    load_stage(1);

    for (int c = 0; c < NC; c++) {
        asm volatile("cp.async.wait_group 1;" ::: "memory");
        __syncthreads();
        if (c + 2 < NC) load_stage(c + 2);
        else asm volatile("cp.async.commit_group;" ::: "memory");

        const uint32_t sb = smbase + (uint32_t)(c % 3) * (STAGEg * 2);
#pragma unroll
        for (int ks = 0; ks < 2; ks++) {
            const int kof = ks * 16;
            uint32_t ah[4][4], al[4][4];
#pragma unroll
            for (int mf = 0; mf < 4; mf++) {
                int row = wr * 64 + mf * 16 + (lane & 15);
                int col = kof + (lane >> 4) * 8;
                uint32_t ad = sb + (uint32_t)(row * RSg + col) * 2;
                ldsm_x4(ah[mf], ad);
                ldsm_x4(al[mf], ad + 64);
            }
            uint32_t bh[2][4], bl[2][4];
#pragma unroll
            for (int np = 0; np < 2; np++) {
                int brow = wc * 32 + np * 16 + ((lane >> 4) & 1) * 8 + (lane & 7);
                int bcol = kof + ((lane >> 3) & 1) * 8;
                uint32_t bd = sb + TENg * 2 + (uint32_t)(brow * RSg + bcol) * 2;
                ldsm_x4(bh[np], bd);
                ldsm_x4(bl[np], bd + 64);
            }
#pragma unroll
            for (int mf = 0; mf < 4; mf++)
#pragma unroll
                for (int np = 0; np < 2; np++) {
                    mma16816(acc[mf][np*2],   ah[mf], &bh[np][0]);
                    mma16816(acc[mf][np*2+1], ah[mf], &bh[np][2]);
                }
#pragma unroll
            for (int mf = 0; mf < 4; mf++)
#pragma unroll
                for (int np = 0; np < 2; np++) {
                    mma16816(acc[mf][np*2],   ah[mf], &bl[np][0]);
                    mma16816(acc[mf][np*2+1], ah[mf], &bl[np][2]);
                }
#pragma unroll
            for (int mf = 0; mf < 4; mf++)
#pragma unroll
                for (int np = 0; np < 2; np++) {
                    mma16816(acc[mf][np*2],   al[mf], &bh[np][0]);
                    mma16816(acc[mf][np*2+1], al[mf], &bh[np][2]);
                }
        }
    }

#pragma unroll
    for (int mf = 0; mf < 4; mf++) {
#pragma unroll
        for (int nf = 0; nf < 4; nf++) {
            int row = rowBase + wr * 64 + mf * 16 + (lane >> 2);
            int col = colBase + wc * 32 + nf * 8 + (lane & 3) * 2;
            *(float2*)(C + (size_t)row * N + col) =
                make_float2(acc[mf][nf][0], acc[mf][nf][1]);
            *(float2*)(C + (size_t)(row + 8) * N + col) =
                make_float2(acc[mf][nf][2], acc[mf][nf][3]);
        }
    }
}

// ---------------- conversions ------------------------------------------------
__global__ void conv_split(const float* __restrict__ x, __nv_bfloat16* __restrict__ hi,
                           __nv_bfloat16* __restrict__ lo, int n)
{
    int i = blockIdx.x * blockDim.x + threadIdx.x;
    if (i >= n) return;
    float v = x[i];
    __nv_bfloat16 h = __float2bfloat16(v);
    hi[i] = h;
    lo[i] = __float2bfloat16(v - __bfloat162float(h));
}

__global__ void convt_split(const float* __restrict__ W, __nv_bfloat16* __restrict__ hi,
                            __nv_bfloat16* __restrict__ lo, int K, int N)
{
    __shared__ float t[32][33];
    int n0 = blockIdx.x * 32, k0 = blockIdx.y * 32;
    for (int r = threadIdx.y; r < 32; r += 8)
        t[r][threadIdx.x] = W[(size_t)(k0 + r) * N + n0 + threadIdx.x];
    __syncthreads();
    for (int r = threadIdx.y; r < 32; r += 8) {
        float v = t[threadIdx.x][r];
        __nv_bfloat16 h = __float2bfloat16(v);
        size_t o = (size_t)(n0 + r) * K + k0 + threadIdx.x;
        hi[o] = h;
        lo[o] = __float2bfloat16(v - __bfloat162float(h));
    }
}

__device__ __forceinline__ void wsplit(__nv_bfloat16* hi, __nv_bfloat16* lo,
                                       size_t off, float v) {
    __nv_bfloat16 h = __float2bfloat16(v);
    hi[off] = h;
    lo[off] = __float2bfloat16(v - __bfloat162float(h));
}

// combine QKV partials + RoPE + bf16 hi/lo split for q,k; also pos -> float.
__global__ void combine_qk(const int* __restrict__ pos)
{
    int idx = blockIdx.x * blockDim.x + threadIdx.x;
    if (idx < S) g_posf[idx] = (float)pos[idx];
    int d48 = idx % 48;
    int rem = idx / 48;
    int s = rem & (S - 1);
    int h = rem >> 11;
    if (h >= NH) return;
    const float* P0 = g_part;
    const float* P1 = g_part + (size_t)S * N_QKV;
    size_t rowb = (size_t)s * N_QKV;
    size_t base = ((size_t)h * S + s) * HD;
    if (d48 < 32) {
        int d = d48;
        int cq = h * HD + d;
        int ck = cq + HID;
        float q1 = P0[rowb + cq]      + P1[rowb + cq];
        float q2 = P0[rowb + cq + 32] + P1[rowb + cq + 32];
        float k1 = P0[rowb + ck]      + P1[rowb + ck];
        float k2 = P0[rowb + ck + 32] + P1[rowb + ck + 32];
        float posf = (float)pos[s];
        float inv  = exp2f(-0.415241011861f * (float)d);
        float ang  = posf * inv;
        float c, sn;
        sincosf(ang, &sn, &c);
        wsplit(g_qh, g_ql, base + d,      q1 * c - q2 * sn);
        wsplit(g_qh, g_ql, base + d + 32, q2 * c + q1 * sn);
        wsplit(g_kh, g_kl, base + d,      k1 * c - k2 * sn);
        wsplit(g_kh, g_kl, base + d + 32, k2 * c + k1 * sn);
    } else {
        int d = d48 + 32;     // 64..79
        int cq = h * HD + d;
        int ck = cq + HID;
        wsplit(g_qh, g_ql, base + d, P0[rowb + cq] + P1[rowb + cq]);
        wsplit(g_kh, g_kl, base + d, P0[rowb + ck] + P1[rowb + ck]);
    }
}

// combine V partials + bf16 hi/lo split
__global__ void combine_v()
{
    int i = blockIdx.x * blockDim.x + threadIdx.x;
    if (i >= S * HID) return;
    int s = i / HID, c = i - s * HID;
    const float* P0 = g_part;
    const float* P1 = g_part + (size_t)S * N_QKV;
    size_t off = (size_t)s * N_QKV + 2 * HID + c;
    float v = P0[off] + P1[off];
    int h = c / HD, d = c - h * HD;
    wsplit(g_vh, g_vl, ((size_t)h * S + s) * HD + d, v);
}

// combine out-proj partials -> d_out
__global__ void combine_out(float* __restrict__ out)
{
    int i = blockIdx.x * blockDim.x + threadIdx.x;
    if (i >= S * HID) return;
    out[i] = g_part[i] + g_part[(size_t)S * HID + i];
}

// ---------------- HMMA flash attention (R13 best config) ---------------------
// Q-tile 64, 128 threads (4 warps), K-tile 64, 2-stage ring, 2 CTAs/SM.
#define AQB 64
#define AKB 64
#define ARS 88
#define T_ELEMS (AKB*ARS)
#define KPOS_OFF (4*T_ELEMS*2)
#define ASTAGE (KPOS_OFF + 256)
#define ATTN_SMEM (2*ASTAGE)

__global__ __launch_bounds__(128, 2)
void attn_mma()
{
    extern __shared__ char smbuf[];
    const int h     = blockIdx.y;
    const int qtile = gridDim.x - 1 - blockIdx.x;
    const int q0    = qtile * AQB;
    const int tid   = threadIdx.x;
    const int wid   = tid >> 5;
    const int lane  = tid & 31;
    const uint32_t sb = smem_u32(smbuf);

    const int r0 = q0 + wid * 16 + (lane >> 2);
    const int cp = (lane & 3) * 2;
    uint32_t qfh[5][4], qfl[5][4];
    {
        const __nv_bfloat16* qhp = g_qh + ((size_t)h * S + r0) * HD;
        const __nv_bfloat16* qlp = g_ql + ((size_t)h * S + r0) * HD;
#pragma unroll
        for (int ks = 0; ks < 5; ks++) {
            int c = ks * 16 + cp;
            qfh[ks][0] = *(const uint32_t*)(qhp + c);
            qfh[ks][1] = *(const uint32_t*)(qhp + 8 * HD + c);
            qfh[ks][2] = *(const uint32_t*)(qhp + c + 8);
            qfh[ks][3] = *(const uint32_t*)(qhp + 8 * HD + c + 8);
            qfl[ks][0] = *(const uint32_t*)(qlp + c);
            qfl[ks][1] = *(const uint32_t*)(qlp + 8 * HD + c);
            qfl[ks][2] = *(const uint32_t*)(qlp + c + 8);
            qfl[ks][3] = *(const uint32_t*)(qlp + 8 * HD + c + 8);
        }
    }
    const float qp0 = g_posf[r0];
    const float qp1 = g_posf[r0 + 8];
    const float slope = exp2f(-0.25f * (float)(h + 1));

    float o[10][4];
#pragma unroll
    for (int i = 0; i < 10; i++)
#pragma unroll
        for (int j = 0; j < 4; j++) o[i][j] = 0.f;
    float m0 = -1e30f, m1 = -1e30f, l0 = 0.f, l1 = 0.f;

    const int NT = qtile + 1;

    auto issue = [&](int t) {
        const uint32_t dst = sb + (uint32_t)(t & 1) * ASTAGE;
        const int kt = t * AKB;
#pragma unroll
        for (int it = 0; it < 20; it++) {
            int idx = it * 128 + tid;
            int tensor = idx / 640;
            int rem = idx - tensor * 640;
            int row = rem / 10, seg = rem - row * 10;
            const __nv_bfloat16* base =
                (tensor == 0) ? g_kh : (tensor == 1) ? g_kl : (tensor == 2) ? g_vh : g_vl;
            const __nv_bfloat16* src = base + ((size_t)h * S + kt + row) * HD + seg * 8;
            cp16(dst + (uint32_t)tensor * (T_ELEMS * 2) + (uint32_t)(row * ARS + seg * 8) * 2, src);
        }
        if (tid < 16) cp16(dst + KPOS_OFF + tid * 16, g_posf + kt + tid * 4);
    };

    issue(0);
    asm volatile("cp.async.commit_group;" ::: "memory");

    for (int t = 0; t < NT; t++) {
        if (t + 1 < NT) issue(t + 1);
        asm volatile("cp.async.commit_group;" ::: "memory");
        asm volatile("cp.async.wait_group 1;" ::: "memory");
        __syncthreads();

        const uint32_t st = sb + (uint32_t)(t & 1) * ASTAGE;
        const float* kposb = (const float*)(smbuf + (size_t)(t & 1) * ASTAGE + KPOS_OFF);

        float accs[8][4];
#pragma unroll
        for (int nf = 0; nf < 8; nf++)
#pragma unroll
            for (int e = 0; e < 4; e++) accs[nf][e] = 0.f;

        const int mq = lane >> 3;
#pragma unroll
        for (int ks = 0; ks < 5; ks++) {
            uint32_t bh[4][4], bl[4][4];
#pragma unroll
            for (int nfp = 0; nfp < 4; nfp++) {
                uint32_t row = (uint32_t)((nfp * 2 + (mq >> 1)) * 8 + (lane & 7));
                uint32_t col = (uint32_t)(ks * 16 + (mq & 1) * 8);
                uint32_t ad = st + (row * ARS + col) * 2;
                ldsm_x4(bh[nfp], ad);
                ldsm_x4(bl[nfp], ad + T_ELEMS * 2);
            }
#pragma unroll
            for (int nfp = 0; nfp < 4; nfp++) {
                mma16816(accs[nfp*2],   qfh[ks], &bh[nfp][0]);
                mma16816(accs[nfp*2+1], qfh[ks], &bh[nfp][2]);
            }
#pragma unroll
            for (int nfp = 0; nfp < 4; nfp++) {
                mma16816(accs[nfp*2],   qfh[ks], &bl[nfp][0]);
                mma16816(accs[nfp*2+1], qfh[ks], &bl[nfp][2]);
            }
#pragma unroll
            for (int nfp = 0; nfp < 4; nfp++) {
                mma16816(accs[nfp*2],   qfl[ks], &bh[nfp][0]);
                mma16816(accs[nfp*2+1], qfl[ks], &bh[nfp][2]);
            }
        }

        float mx0 = -1e30f, mx1 = -1e30f;
#pragma unroll
        for (int nf = 0; nf < 8; nf++) {
            float2 kc = *(const float2*)(kposb + nf * 8 + cp);
            float b0 = slope * kc.x, b1 = slope * kc.y;
            float s0 = (kc.x <= qp0) ? fmaf(accs[nf][0], SCALE, b0) : -1e30f;
            float s1 = (kc.y <= qp0) ? fmaf(accs[nf][1], SCALE, b1) : -1e30f;
            float s2 = (kc.x <= qp1) ? fmaf(accs[nf][2], SCALE, b0) : -1e30f;
            float s3 = (kc.y <= qp1) ? fmaf(accs[nf][3], SCALE, b1) : -1e30f;
            accs[nf][0] = s0; accs[nf][1] = s1; accs[nf][2] = s2; accs[nf][3] = s3;
            mx0 = fmaxf(mx0, fmaxf(s0, s1));
            mx1 = fmaxf(mx1, fmaxf(s2, s3));
        }
        mx0 = fmaxf(mx0, __shfl_xor_sync(0xFFFFFFFFu, mx0, 1));
        mx0 = fmaxf(mx0, __shfl_xor_sync(0xFFFFFFFFu, mx0, 2));
        mx1 = fmaxf(mx1, __shfl_xor_sync(0xFFFFFFFFu, mx1, 1));
        mx1 = fmaxf(mx1, __shfl_xor_sync(0xFFFFFFFFu, mx1, 2));

        float m0n = fmaxf(m0, mx0), m1n = fmaxf(m1, mx1);
        float c0 = __expf(m0 - m0n), c1 = __expf(m1 - m1n);
        m0 = m0n; m1 = m1n;

        float sum0 = 0.f, sum1 = 0.f;
#pragma unroll
        for (int nf = 0; nf < 8; nf++) {
            float p0 = __expf(accs[nf][0] - m0);
            float p1 = __expf(accs[nf][1] - m0);
            float p2 = __expf(accs[nf][2] - m1);
            float p3 = __expf(accs[nf][3] - m1);
            accs[nf][0] = p0; accs[nf][1] = p1; accs[nf][2] = p2; accs[nf][3] = p3;
            sum0 += p0 + p1; sum1 += p2 + p3;
        }
        l0 = l0 * c0 + sum0;
        l1 = l1 * c1 + sum1;
#pragma unroll
        for (int nf = 0; nf < 10; nf++) {
            o[nf][0] *= c0; o[nf][1] *= c0;
            o[nf][2] *= c1; o[nf][3] *= c1;
        }

        uint32_t ph[4][4], pl[4][4];
#pragma unroll
        for (int ks2 = 0; ks2 < 4; ks2++) {
            split2(accs[2*ks2][0],   accs[2*ks2][1],   ph[ks2][0], pl[ks2][0]);
            split2(accs[2*ks2][2],   accs[2*ks2][3],   ph[ks2][1], pl[ks2][1]);
            split2(accs[2*ks2+1][0], accs[2*ks2+1][1], ph[ks2][2], pl[ks2][2]);
            split2(accs[2*ks2+1][2], accs[2*ks2+1][3], ph[ks2][3], pl[ks2][3]);
        }

#pragma unroll
        for (int ks2 = 0; ks2 < 4; ks2++) {
            uint32_t bvh[5][4], bvl[5][4];
#pragma unroll
            for (int nfp = 0; nfp < 5; nfp++) {
                uint32_t row = (uint32_t)(ks2 * 16 + (mq & 1) * 8 + (lane & 7));
                uint32_t col = (uint32_t)((nfp * 2 + (mq >> 1)) * 8);
                uint32_t ad = st + 2 * (T_ELEMS * 2) + (row * ARS + col) * 2;
                ldsm_x4t(bvh[nfp], ad);
                ldsm_x4t(bvl[nfp], ad + T_ELEMS * 2);
            }
#pragma unroll
            for (int nfp = 0; nfp < 5; nfp++) {
                mma16816(o[nfp*2],   ph[ks2], &bvh[nfp][0]);
                mma16816(o[nfp*2+1], ph[ks2], &bvh[nfp][2]);
            }
#pragma unroll
            for (int nfp = 0; nfp < 5; nfp++) {
                mma16816(o[nfp*2],   ph[ks2], &bvl[nfp][0]);
                mma16816(o[nfp*2+1], ph[ks2], &bvl[nfp][2]);
            }
#pragma unroll
            for (int nfp = 0; nfp < 5; nfp++) {
                mma16816(o[nfp*2],   pl[ks2], &bvh[nfp][0]);
                mma16816(o[nfp*2+1], pl[ks2], &bvh[nfp][2]);
            }
        }
        __syncthreads();
    }

    l0 += __shfl_xor_sync(0xFFFFFFFFu, l0, 1);
    l0 += __shfl_xor_sync(0xFFFFFFFFu, l0, 2);
    l1 += __shfl_xor_sync(0xFFFFFFFFu, l1, 1);
    l1 += __shfl_xor_sync(0xFFFFFFFFu, l1, 2);
    float inv0 = 1.f / l0, inv1 = 1.f / l1;

    size_t ob0 = (size_t)r0 * HID + h * HD;
    size_t ob1 = (size_t)(r0 + 8) * HID + h * HD;
#pragma unroll
    for (int nf = 0; nf < 10; nf++) {
        int col = nf * 8 + cp;
        uint32_t hi, lo;
        split2(o[nf][0] * inv0, o[nf][1] * inv0, hi, lo);
        *(uint32_t*)&g_at_hi[ob0 + col] = hi;
        *(uint32_t*)&g_at_lo[ob0 + col] = lo;
        split2(o[nf][2] * inv1, o[nf][3] * inv1, hi, lo);
        *(uint32_t*)&g_at_hi[ob1 + col] = hi;
        *(uint32_t*)&g_at_lo[ob1 + col] = lo;
    }
}

// ---------------- launch -------------------------------------------------------
extern "C" void kernel_launch(void* const* d_in, const int* in_sizes, int n_in,
                              void* d_out, int out_size)
{
    const int*   pos  = nullptr;
    const float* hs   = nullptr;
    const float* wqkv = nullptr;
    const float* wout = nullptr;
    for (int i = 0; i < n_in; i++) {
        switch (in_sizes[i]) {
            case S:           pos  = (const int*)d_in[i];   break;
            case S * HID:     hs   = (const float*)d_in[i]; break;
            case HID * N_QKV: wqkv = (const float*)d_in[i]; break;
            case HID * HID:   wout = (const float*)d_in[i]; break;
        }
    }
    if (!pos || !hs || !wqkv || !wout) return;

    cudaFuncSetAttribute(mma_gemm, cudaFuncAttributeMaxDynamicSharedMemorySize, GEMM_SMEM);
    cudaFuncSetAttribute(attn_mma, cudaFuncAttributeMaxDynamicSharedMemorySize, ATTN_SMEM);

    __nv_bfloat16 *ahi, *alo, *wqh, *wql, *woh, *wol, *ath, *atl;
    float* part;
    cudaGetSymbolAddress((void**)&ahi, g_a_hi);
    cudaGetSymbolAddress((void**)&alo, g_a_lo);
    cudaGetSymbolAddress((void**)&wqh, g_wqkv_hi);
    cudaGetSymbolAddress((void**)&wql, g_wqkv_lo);
    cudaGetSymbolAddress((void**)&woh, g_wout_hi);
    cudaGetSymbolAddress((void**)&wol, g_wout_lo);
    cudaGetSymbolAddress((void**)&ath, g_at_hi);
    cudaGetSymbolAddress((void**)&atl, g_at_lo);
    cudaGetSymbolAddress((void**)&part, g_part);

    // conversions
    conv_split<<<(S * HID) / 256, 256>>>(hs, ahi, alo, S * HID);
    convt_split<<<dim3(N_QKV / 32, HID / 32), dim3(32, 8)>>>(wqkv, wqh, wql, HID, N_QKV);
    convt_split<<<dim3(HID / 32, HID / 32), dim3(32, 8)>>>(wout, woh, wol, HID, HID);

    // 1) QKV projection, split-K=2 -> partials
    mma_gemm<<<dim3(N_QKV / BNg, S / BMg, 2), 256, GEMM_SMEM>>>(ahi, alo, wqh, wql, part, HID, N_QKV, HID / 2);

    // 2) combine partials: q,k (+rope+split) and v (+split); pos -> float
    combine_qk<<<(NH * S * 48) / 256, 256>>>(pos);
    combine_v<<<(S * HID) / 256, 256>>>();

    // 3) flash attention (R13 config), epilogue writes bf16 hi/lo
    attn_mma<<<dim3(S / AQB, NH), 128, ATTN_SMEM>>>();

    // 4) output projection, split-K=2 -> partials, then combine into d_out
    mma_gemm<<<dim3(HID / BNg, S / BMg, 2), 256, GEMM_SMEM>>>(ath, atl, woh, wol, part, HID, HID, HID / 2);
    combine_out<<<(S * HID) / 256, 256>>>((float*)d_out);
}

// round 16
// speedup vs baseline: 1.0991x; 1.0233x over previous
#include <cuda_runtime.h>
#include <cuda_bf16.h>
#include <cstdint>

// Problem constants
#define S    2048
#define HID  2560
#define NH   32
#define HD   80
#define N_QKV (3*HID)          // 7680
#define SCALE 0.11180339887498949f   // 80^-0.5

// ---------------- scratch (device globals; no allocs allowed) ---------------
__device__ float g_part[2 * S * N_QKV];     // split-K partials (holds 4*S*HID too)
__device__ float g_posf[S];

__device__ __nv_bfloat16 g_a_hi[S * HID],      g_a_lo[S * HID];
__device__ __nv_bfloat16 g_wqkv_hi[N_QKV*HID], g_wqkv_lo[N_QKV*HID];
__device__ __nv_bfloat16 g_wout_hi[HID*HID],   g_wout_lo[HID*HID];
__device__ __nv_bfloat16 g_at_hi[S * HID],     g_at_lo[S * HID];

__device__ __nv_bfloat16 g_qh[NH*S*HD], g_ql[NH*S*HD];
__device__ __nv_bfloat16 g_kh[NH*S*HD], g_kl[NH*S*HD];
__device__ __nv_bfloat16 g_vh[NH*S*HD], g_vl[NH*S*HD];

// ---------------- PTX helpers ------------------------------------------------
__device__ __forceinline__ uint32_t smem_u32(const void* p) {
    return (uint32_t)__cvta_generic_to_shared((void*)p);
}
__device__ __forceinline__ void cp16(uint32_t s, const void* g) {
    asm volatile("cp.async.cg.shared.global [%0], [%1], 16;" :: "r"(s), "l"(g) : "memory");
}
__device__ __forceinline__ void ldsm_x4(uint32_t* r, uint32_t addr) {
    asm volatile("ldmatrix.sync.aligned.m8n8.x4.shared.b16 {%0,%1,%2,%3}, [%4];"
                 : "=r"(r[0]), "=r"(r[1]), "=r"(r[2]), "=r"(r[3]) : "r"(addr));
}
__device__ __forceinline__ void ldsm_x4t(uint32_t* r, uint32_t addr) {
    asm volatile("ldmatrix.sync.aligned.m8n8.x4.trans.shared.b16 {%0,%1,%2,%3}, [%4];"
                 : "=r"(r[0]), "=r"(r[1]), "=r"(r[2]), "=r"(r[3]) : "r"(addr));
}
__device__ __forceinline__ void mma16816(float* d, const uint32_t* a, const uint32_t* b) {
    asm volatile("mma.sync.aligned.m16n8k16.row.col.f32.bf16.bf16.f32 "
                 "{%0,%1,%2,%3}, {%4,%5,%6,%7}, {%8,%9}, {%0,%1,%2,%3};"
                 : "+f"(d[0]), "+f"(d[1]), "+f"(d[2]), "+f"(d[3])
                 : "r"(a[0]), "r"(a[1]), "r"(a[2]), "r"(a[3]), "r"(b[0]), "r"(b[1]));
}
__device__ __forceinline__ void split2(float a, float b, uint32_t& hi, uint32_t& lo) {
    __nv_bfloat162 h, l;
    h.x = __float2bfloat16(a);
    h.y = __float2bfloat16(b);
    l.x = __float2bfloat16(a - __bfloat162float(h.x));
    l.y = __float2bfloat16(b - __bfloat162float(h.y));
    hi = *(uint32_t*)&h;
    lo = *(uint32_t*)&l;
}

// ---------------- HMMA GEMM with split-K -------------------------------------
#define BMg 128
#define BNg 128
#define RSg 72
#define TENg (128*RSg)
#define STAGEg (2*TENg)
#define GEMM_SMEM (3*STAGEg*2)

__global__ __launch_bounds__(256, 2)
void mma_gemm(const __nv_bfloat16* __restrict__ Ahi, const __nv_bfloat16* __restrict__ Alo,
              const __nv_bfloat16* __restrict__ Bhi, const __nv_bfloat16* __restrict__ Blo,
              float* __restrict__ C, int K, int N, int KS)
{
    extern __shared__ __align__(128) __nv_bfloat16 sm[];
    const int tid  = threadIdx.x;
    const int wid  = tid >> 5;
    const int lane = tid & 31;
    const int wr   = wid >> 2;
    const int wc   = wid & 3;
    const int rowBase = blockIdx.y * BMg;
    const int colBase = blockIdx.x * BNg;
    const int koff    = blockIdx.z * KS;
    C += (size_t)blockIdx.z * (size_t)(gridDim.y * BMg) * N;
    const uint32_t smbase = smem_u32(sm);

    float acc[4][4][4];
#pragma unroll
    for (int i = 0; i < 4; i++)
#pragma unroll
        for (int j = 0; j < 4; j++)
#pragma unroll
            for (int k = 0; k < 4; k++) acc[i][j][k] = 0.f;

    const int NC = KS >> 5;

    auto load_stage = [&](int c) {
        const int kt = koff + (c << 5);
        const uint32_t sb = smbase + (uint32_t)(c % 3) * (STAGEg * 2);
#pragma unroll
        for (int t = 0; t < 8; t++) {
            int idx = tid + t * 256;
            int isB = idx >> 10;
            int rem = idx & 1023;
            int hl  = rem >> 9;
            int r2  = rem & 511;
            int row = r2 >> 2, seg = r2 & 3;
            const __nv_bfloat16* src = isB
                ? ((hl ? Blo : Bhi) + (size_t)(colBase + row) * K + kt + seg * 8)
                : ((hl ? Alo : Ahi) + (size_t)(rowBase + row) * K + kt + seg * 8);
            cp16(sb + (uint32_t)(isB * TENg + row * RSg + hl * 32 + seg * 8) * 2, src);
        }
        asm volatile("cp.async.commit_group;" ::: "memory");
    };

    load_stage(0);
    load_stage(1);

    for (int c = 0; c < NC; c++) {
        asm volatile("cp.async.wait_group 1;" ::: "memory");
        __syncthreads();
        if (c + 2 < NC) load_stage(c + 2);
        else asm volatile("cp.async.commit_group;" ::: "memory");

        const uint32_t sb = smbase + (uint32_t)(c % 3) * (STAGEg * 2);
#pragma unroll
        for (int ks = 0; ks < 2; ks++) {
            const int kof = ks * 16;
            uint32_t ah[4][4], al[4][4];
#pragma unroll
            for (int mf = 0; mf < 4; mf++) {
                int row = wr * 64 + mf * 16 + (lane & 15);
                int col = kof + (lane >> 4) * 8;
                uint32_t ad = sb + (uint32_t)(row * RSg + col) * 2;
                ldsm_x4(ah[mf], ad);
                ldsm_x4(al[mf], ad + 64);
            }
            uint32_t bh[2][4], bl[2][4];
#pragma unroll
            for (int np = 0; np < 2; np++) {
                int brow = wc * 32 + np * 16 + ((lane >> 4) & 1) * 8 + (lane & 7);
                int bcol = kof + ((lane >> 3) & 1) * 8;
                uint32_t bd = sb + TENg * 2 + (uint32_t)(brow * RSg + bcol) * 2;
                ldsm_x4(bh[np], bd);
                ldsm_x4(bl[np], bd + 64);
            }
#pragma unroll
            for (int mf = 0; mf < 4; mf++)
#pragma unroll
                for (int np = 0; np < 2; np++) {
                    mma16816(acc[mf][np*2],   ah[mf], &bh[np][0]);
                    mma16816(acc[mf][np*2+1], ah[mf], &bh[np][2]);
                }
#pragma unroll
            for (int mf = 0; mf < 4; mf++)
#pragma unroll
                for (int np = 0; np < 2; np++) {
                    mma16816(acc[mf][np*2],   ah[mf], &bl[np][0]);
                    mma16816(acc[mf][np*2+1], ah[mf], &bl[np][2]);
                }
#pragma unroll
            for (int mf = 0; mf < 4; mf++)
#pragma unroll
                for (int np = 0; np < 2; np++) {
                    mma16816(acc[mf][np*2],   al[mf], &bh[np][0]);
                    mma16816(acc[mf][np*2+1], al[mf], &bh[np][2]);
                }
        }
    }

#pragma unroll
    for (int mf = 0; mf < 4; mf++) {
#pragma unroll
        for (int nf = 0; nf < 4; nf++) {
            int row = rowBase + wr * 64 + mf * 16 + (lane >> 2);
            int col = colBase + wc * 32 + nf * 8 + (lane & 3) * 2;
            *(float2*)(C + (size_t)row * N + col) =
                make_float2(acc[mf][nf][0], acc[mf][nf][1]);
            *(float2*)(C + (size_t)(row + 8) * N + col) =
                make_float2(acc[mf][nf][2], acc[mf][nf][3]);
        }
    }
}

// ---------------- conversions ------------------------------------------------
__global__ void conv_split(const float* __restrict__ x, __nv_bfloat16* __restrict__ hi,
                           __nv_bfloat16* __restrict__ lo, int n)
{
    int i = blockIdx.x * blockDim.x + threadIdx.x;
    if (i >= n) return;
    float v = x[i];
    __nv_bfloat16 h = __float2bfloat16(v);
    hi[i] = h;
    lo[i] = __float2bfloat16(v - __bfloat162float(h));
}

__global__ void convt_split(const float* __restrict__ W, __nv_bfloat16* __restrict__ hi,
                            __nv_bfloat16* __restrict__ lo, int K, int N)
{
    __shared__ float t[32][33];
    int n0 = blockIdx.x * 32, k0 = blockIdx.y * 32;
    for (int r = threadIdx.y; r < 32; r += 8)
        t[r][threadIdx.x] = W[(size_t)(k0 + r) * N + n0 + threadIdx.x];
    __syncthreads();
    for (int r = threadIdx.y; r < 32; r += 8) {
        float v = t[threadIdx.x][r];
        __nv_bfloat16 h = __float2bfloat16(v);
        size_t o = (size_t)(n0 + r) * K + k0 + threadIdx.x;
        hi[o] = h;
        lo[o] = __float2bfloat16(v - __bfloat162float(h));
    }
}

__device__ __forceinline__ void wsplit(__nv_bfloat16* hi, __nv_bfloat16* lo,
                                       size_t off, float v) {
    __nv_bfloat16 h = __float2bfloat16(v);
    hi[off] = h;
    lo[off] = __float2bfloat16(v - __bfloat162float(h));
}

// combine QKV partials + RoPE + bf16 hi/lo split for q,k; also pos -> float.
__global__ void combine_qk(const int* __restrict__ pos)
{
    int idx = blockIdx.x * blockDim.x + threadIdx.x;
    if (idx < S) g_posf[idx] = (float)pos[idx];
    int d48 = idx % 48;
    int rem = idx / 48;
    int s = rem & (S - 1);
    int h = rem >> 11;
    if (h >= NH) return;
    const float* P0 = g_part;
    const float* P1 = g_part + (size_t)S * N_QKV;
    size_t rowb = (size_t)s * N_QKV;
    size_t base = ((size_t)h * S + s) * HD;
    if (d48 < 32) {
        int d = d48;
        int cq = h * HD + d;
        int ck = cq + HID;
        float q1 = P0[rowb + cq]      + P1[rowb + cq];
        float q2 = P0[rowb + cq + 32] + P1[rowb + cq + 32];
        float k1 = P0[rowb + ck]      + P1[rowb + ck];
        float k2 = P0[rowb + ck + 32] + P1[rowb + ck + 32];
        float posf = (float)pos[s];
        float inv  = exp2f(-0.415241011861f * (float)d);
        float ang  = posf * inv;
        float c, sn;
        sincosf(ang, &sn, &c);
        wsplit(g_qh, g_ql, base + d,      q1 * c - q2 * sn);
        wsplit(g_qh, g_ql, base + d + 32, q2 * c + q1 * sn);
        wsplit(g_kh, g_kl, base + d,      k1 * c - k2 * sn);
        wsplit(g_kh, g_kl, base + d + 32, k2 * c + k1 * sn);
    } else {
        int d = d48 + 32;
        int cq = h * HD + d;
        int ck = cq + HID;
        wsplit(g_qh, g_ql, base + d, P0[rowb + cq] + P1[rowb + cq]);
        wsplit(g_kh, g_kl, base + d, P0[rowb + ck] + P1[rowb + ck]);
    }
}

// combine V partials + bf16 hi/lo split
__global__ void combine_v()
{
    int i = blockIdx.x * blockDim.x + threadIdx.x;
    if (i >= S * HID) return;
    int s = i / HID, c = i - s * HID;
    const float* P0 = g_part;
    const float* P1 = g_part + (size_t)S * N_QKV;
    size_t off = (size_t)s * N_QKV + 2 * HID + c;
    float v = P0[off] + P1[off];
    int h = c / HD, d = c - h * HD;
    wsplit(g_vh, g_vl, ((size_t)h * S + s) * HD + d, v);
}

// combine out-proj partials (4 planes) -> d_out, float4 vectorized
__global__ void combine_out(float* __restrict__ out)
{
    int i = blockIdx.x * blockDim.x + threadIdx.x;   // float4 index
    if (i >= (S * HID) / 4) return;
    const float4* P0 = (const float4*)g_part;
    const float4* P1 = (const float4*)(g_part + (size_t)S * HID);
    const float4* P2 = (const float4*)(g_part + 2 * (size_t)S * HID);
    const float4* P3 = (const float4*)(g_part + 3 * (size_t)S * HID);
    float4 a = P0[i], b = P1[i], c = P2[i], d = P3[i];
    ((float4*)out)[i] = make_float4(a.x + b.x + c.x + d.x,
                                    a.y + b.y + c.y + d.y,
                                    a.z + b.z + c.z + d.z,
                                    a.w + b.w + c.w + d.w);
}

// ---------------- HMMA flash attention (R13 best config) ---------------------
#define AQB 64
#define AKB 64
#define ARS 88
#define T_ELEMS (AKB*ARS)
#define KPOS_OFF (4*T_ELEMS*2)
#define ASTAGE (KPOS_OFF + 256)
#define ATTN_SMEM (2*ASTAGE)

__global__ __launch_bounds__(128, 2)
void attn_mma()
{
    extern __shared__ char smbuf[];
    const int h     = blockIdx.y;
    const int qtile = gridDim.x - 1 - blockIdx.x;
    const int q0    = qtile * AQB;
    const int tid   = threadIdx.x;
    const int wid   = tid >> 5;
    const int lane  = tid & 31;
    const uint32_t sb = smem_u32(smbuf);

    const int r0 = q0 + wid * 16 + (lane >> 2);
    const int cp = (lane & 3) * 2;
    uint32_t qfh[5][4], qfl[5][4];
    {
        const __nv_bfloat16* qhp = g_qh + ((size_t)h * S + r0) * HD;
        const __nv_bfloat16* qlp = g_ql + ((size_t)h * S + r0) * HD;
#pragma unroll
        for (int ks = 0; ks < 5; ks++) {
            int c = ks * 16 + cp;
            qfh[ks][0] = *(const uint32_t*)(qhp + c);
            qfh[ks][1] = *(const uint32_t*)(qhp + 8 * HD + c);
            qfh[ks][2] = *(const uint32_t*)(qhp + c + 8);
            qfh[ks][3] = *(const uint32_t*)(qhp + 8 * HD + c + 8);
            qfl[ks][0] = *(const uint32_t*)(qlp + c);
            qfl[ks][1] = *(const uint32_t*)(qlp + 8 * HD + c);
            qfl[ks][2] = *(const uint32_t*)(qlp + c + 8);
            qfl[ks][3] = *(const uint32_t*)(qlp + 8 * HD + c + 8);
        }
    }
    const float qp0 = g_posf[r0];
    const float qp1 = g_posf[r0 + 8];
    const float slope = exp2f(-0.25f * (float)(h + 1));

    float o[10][4];
#pragma unroll
    for (int i = 0; i < 10; i++)
#pragma unroll
        for (int j = 0; j < 4; j++) o[i][j] = 0.f;
    float m0 = -1e30f, m1 = -1e30f, l0 = 0.f, l1 = 0.f;

    const int NT = qtile + 1;

    auto issue = [&](int t) {
        const uint32_t dst = sb + (uint32_t)(t & 1) * ASTAGE;
        const int kt = t * AKB;
#pragma unroll
        for (int it = 0; it < 20; it++) {
            int idx = it * 128 + tid;
            int tensor = idx / 640;
            int rem = idx - tensor * 640;
            int row = rem / 10, seg = rem - row * 10;
            const __nv_bfloat16* base =
                (tensor == 0) ? g_kh : (tensor == 1) ? g_kl : (tensor == 2) ? g_vh : g_vl;
            const __nv_bfloat16* src = base + ((size_t)h * S + kt + row) * HD + seg * 8;
            cp16(dst + (uint32_t)tensor * (T_ELEMS * 2) + (uint32_t)(row * ARS + seg * 8) * 2, src);
        }
        if (tid < 16) cp16(dst + KPOS_OFF + tid * 16, g_posf + kt + tid * 4);
    };

    issue(0);
    asm volatile("cp.async.commit_group;" ::: "memory");

    for (int t = 0; t < NT; t++) {
        if (t + 1 < NT) issue(t + 1);
        asm volatile("cp.async.commit_group;" ::: "memory");
        asm volatile("cp.async.wait_group 1;" ::: "memory");
        __syncthreads();

        const uint32_t st = sb + (uint32_t)(t & 1) * ASTAGE;
        const float* kposb = (const float*)(smbuf + (size_t)(t & 1) * ASTAGE + KPOS_OFF);

        float accs[8][4];
#pragma unroll
        for (int nf = 0; nf < 8; nf++)
#pragma unroll
            for (int e = 0; e < 4; e++) accs[nf][e] = 0.f;

        const int mq = lane >> 3;
#pragma unroll
        for (int ks = 0; ks < 5; ks++) {
            uint32_t bh[4][4], bl[4][4];
#pragma unroll
            for (int nfp = 0; nfp < 4; nfp++) {
                uint32_t row = (uint32_t)((nfp * 2 + (mq >> 1)) * 8 + (lane & 7));
                uint32_t col = (uint32_t)(ks * 16 + (mq & 1) * 8);
                uint32_t ad = st + (row * ARS + col) * 2;
                ldsm_x4(bh[nfp], ad);
                ldsm_x4(bl[nfp], ad + T_ELEMS * 2);
            }
#pragma unroll
            for (int nfp = 0; nfp < 4; nfp++) {
                mma16816(accs[nfp*2],   qfh[ks], &bh[nfp][0]);
                mma16816(accs[nfp*2+1], qfh[ks], &bh[nfp][2]);
            }
#pragma unroll
            for (int nfp = 0; nfp < 4; nfp++) {
                mma16816(accs[nfp*2],   qfh[ks], &bl[nfp][0]);
                mma16816(accs[nfp*2+1], qfh[ks], &bl[nfp][2]);
            }
#pragma unroll
            for (int nfp = 0; nfp < 4; nfp++) {
                mma16816(accs[nfp*2],   qfl[ks], &bh[nfp][0]);
                mma16816(accs[nfp*2+1], qfl[ks], &bh[nfp][2]);
            }
        }

        float mx0 = -1e30f, mx1 = -1e30f;
#pragma unroll
        for (int nf = 0; nf < 8; nf++) {
            float2 kc = *(const float2*)(kposb + nf * 8 + cp);
            float b0 = slope * kc.x, b1 = slope * kc.y;
            float s0 = (kc.x <= qp0) ? fmaf(accs[nf][0], SCALE, b0) : -1e30f;
            float s1 = (kc.y <= qp0) ? fmaf(accs[nf][1], SCALE, b1) : -1e30f;
            float s2 = (kc.x <= qp1) ? fmaf(accs[nf][2], SCALE, b0) : -1e30f;
            float s3 = (kc.y <= qp1) ? fmaf(accs[nf][3], SCALE, b1) : -1e30f;
            accs[nf][0] = s0; accs[nf][1] = s1; accs[nf][2] = s2; accs[nf][3] = s3;
            mx0 = fmaxf(mx0, fmaxf(s0, s1));
            mx1 = fmaxf(mx1, fmaxf(s2, s3));
        }
        mx0 = fmaxf(mx0, __shfl_xor_sync(0xFFFFFFFFu, mx0, 1));
        mx0 = fmaxf(mx0, __shfl_xor_sync(0xFFFFFFFFu, mx0, 2));
        mx1 = fmaxf(mx1, __shfl_xor_sync(0xFFFFFFFFu, mx1, 1));
        mx1 = fmaxf(mx1, __shfl_xor_sync(0xFFFFFFFFu, mx1, 2));

        float m0n = fmaxf(m0, mx0), m1n = fmaxf(m1, mx1);
        float c0 = __expf(m0 - m0n), c1 = __expf(m1 - m1n);
        m0 = m0n; m1 = m1n;

        float sum0 = 0.f, sum1 = 0.f;
#pragma unroll
        for (int nf = 0; nf < 8; nf++) {
            float p0 = __expf(accs[nf][0] - m0);
            float p1 = __expf(accs[nf][1] - m0);
            float p2 = __expf(accs[nf][2] - m1);
            float p3 = __expf(accs[nf][3] - m1);
            accs[nf][0] = p0; accs[nf][1] = p1; accs[nf][2] = p2; accs[nf][3] = p3;
            sum0 += p0 + p1; sum1 += p2 + p3;
        }
        l0 = l0 * c0 + sum0;
        l1 = l1 * c1 + sum1;
#pragma unroll
        for (int nf = 0; nf < 10; nf++) {
            o[nf][0] *= c0; o[nf][1] *= c0;
            o[nf][2] *= c1; o[nf][3] *= c1;
        }

        uint32_t ph[4][4], pl[4][4];
#pragma unroll
        for (int ks2 = 0; ks2 < 4; ks2++) {
            split2(accs[2*ks2][0],   accs[2*ks2][1],   ph[ks2][0], pl[ks2][0]);
            split2(accs[2*ks2][2],   accs[2*ks2][3],   ph[ks2][1], pl[ks2][1]);
            split2(accs[2*ks2+1][0], accs[2*ks2+1][1], ph[ks2][2], pl[ks2][2]);
            split2(accs[2*ks2+1][2], accs[2*ks2+1][3], ph[ks2][3], pl[ks2][3]);
        }

#pragma unroll
        for (int ks2 = 0; ks2 < 4; ks2++) {
            uint32_t bvh[5][4], bvl[5][4];
#pragma unroll
            for (int nfp = 0; nfp < 5; nfp++) {
                uint32_t row = (uint32_t)(ks2 * 16 + (mq & 1) * 8 + (lane & 7));
                uint32_t col = (uint32_t)((nfp * 2 + (mq >> 1)) * 8);
                uint32_t ad = st + 2 * (T_ELEMS * 2) + (row * ARS + col) * 2;
                ldsm_x4t(bvh[nfp], ad);
                ldsm_x4t(bvl[nfp], ad + T_ELEMS * 2);
            }
#pragma unroll
            for (int nfp = 0; nfp < 5; nfp++) {
                mma16816(o[nfp*2],   ph[ks2], &bvh[nfp][0]);
                mma16816(o[nfp*2+1], ph[ks2], &bvh[nfp][2]);
            }
#pragma unroll
            for (int nfp = 0; nfp < 5; nfp++) {
                mma16816(o[nfp*2],   ph[ks2], &bvl[nfp][0]);
                mma16816(o[nfp*2+1], ph[ks2], &bvl[nfp][2]);
            }
#pragma unroll
            for (int nfp = 0; nfp < 5; nfp++) {
                mma16816(o[nfp*2],   pl[ks2], &bvh[nfp][0]);
                mma16816(o[nfp*2+1], pl[ks2], &bvh[nfp][2]);
            }
        }
        __syncthreads();
    }

    l0 += __shfl_xor_sync(0xFFFFFFFFu, l0, 1);
    l0 += __shfl_xor_sync(0xFFFFFFFFu, l0, 2);
    l1 += __shfl_xor_sync(0xFFFFFFFFu, l1, 1);
    l1 += __shfl_xor_sync(0xFFFFFFFFu, l1, 2);
    float inv0 = 1.f / l0, inv1 = 1.f / l1;

    size_t ob0 = (size_t)r0 * HID + h * HD;
    size_t ob1 = (size_t)(r0 + 8) * HID + h * HD;
#pragma unroll
    for (int nf = 0; nf < 10; nf++) {
        int col = nf * 8 + cp;
        uint32_t hi, lo;
        split2(o[nf][0] * inv0, o[nf][1] * inv0, hi, lo);
        *(uint32_t*)&g_at_hi[ob0 + col] = hi;
        *(uint32_t*)&g_at_lo[ob0 + col] = lo;
        split2(o[nf][2] * inv1, o[nf][3] * inv1, hi, lo);
        *(uint32_t*)&g_at_hi[ob1 + col] = hi;
        *(uint32_t*)&g_at_lo[ob1 + col] = lo;
    }
}

// ---------------- launch -------------------------------------------------------
extern "C" void kernel_launch(void* const* d_in, const int* in_sizes, int n_in,
                              void* d_out, int out_size)
{
    const int*   pos  = nullptr;
    const float* hs   = nullptr;
    const float* wqkv = nullptr;
    const float* wout = nullptr;
    for (int i = 0; i < n_in; i++) {
        switch (in_sizes[i]) {
            case S:           pos  = (const int*)d_in[i];   break;
            case S * HID:     hs   = (const float*)d_in[i]; break;
            case HID * N_QKV: wqkv = (const float*)d_in[i]; break;
            case HID * HID:   wout = (const float*)d_in[i]; break;
        }
    }
    if (!pos || !hs || !wqkv || !wout) return;

    cudaFuncSetAttribute(mma_gemm, cudaFuncAttributeMaxDynamicSharedMemorySize, GEMM_SMEM);
    cudaFuncSetAttribute(attn_mma, cudaFuncAttributeMaxDynamicSharedMemorySize, ATTN_SMEM);

    __nv_bfloat16 *ahi, *alo, *wqh, *wql, *woh, *wol, *ath, *atl;
    float* part;
    cudaGetSymbolAddress((void**)&ahi, g_a_hi);
    cudaGetSymbolAddress((void**)&alo, g_a_lo);
    cudaGetSymbolAddress((void**)&wqh, g_wqkv_hi);
    cudaGetSymbolAddress((void**)&wql, g_wqkv_lo);
    cudaGetSymbolAddress((void**)&woh, g_wout_hi);
    cudaGetSymbolAddress((void**)&wol, g_wout_lo);
    cudaGetSymbolAddress((void**)&ath, g_at_hi);
    cudaGetSymbolAddress((void**)&atl, g_at_lo);
    cudaGetSymbolAddress((void**)&part, g_part);

    // conversions
    conv_split<<<(S * HID) / 256, 256>>>(hs, ahi, alo, S * HID);
    convt_split<<<dim3(N_QKV / 32, HID / 32), dim3(32, 8)>>>(wqkv, wqh, wql, HID, N_QKV);
    convt_split<<<dim3(HID / 32, HID / 32), dim3(32, 8)>>>(wout, woh, wol, HID, HID);

    // 1) QKV projection, split-K=2 -> partials
    mma_gemm<<<dim3(N_QKV / BNg, S / BMg, 2), 256, GEMM_SMEM>>>(ahi, alo, wqh, wql, part, HID, N_QKV, HID / 2);

    // 2) combine partials: q,k (+rope+split) and v (+split); pos -> float
    combine_qk<<<(NH * S * 48) / 256, 256>>>(pos);
    combine_v<<<(S * HID) / 256, 256>>>();

    // 3) flash attention (R13 config), epilogue writes bf16 hi/lo
    attn_mma<<<dim3(S / AQB, NH), 128, ATTN_SMEM>>>();

    // 4) output projection, split-K=4 -> partials, then combine into d_out
    mma_gemm<<<dim3(HID / BNg, S / BMg, 4), 256, GEMM_SMEM>>>(ath, atl, woh, wol, part, HID, HID, HID / 4);
    combine_out<<<(S * HID) / 1024, 256>>>((float*)d_out);
}